// round 7
// baseline (speedup 1.0000x reference)
#include <cuda_runtime.h>
#include <cuda_bf16.h>
#include <cstdint>

#define DINLINE __device__ __forceinline__

// ---------------------------------------------------------------------------
// Problem constants
// ---------------------------------------------------------------------------
constexpr int NTOK  = 8192;   // B*S tokens
constexpr int IN    = 4096;
constexpr int OUT   = 4096;
constexpr int POOLS = 128;
constexpr int SEGS  = 3;      // bf16 split: xh*wh + xh*wl + xl*wh

constexpr int BK = 64;        // bf16 per k-chunk -> 128B rows
constexpr int CHUNKS_PER_SEG = IN / BK;               // 64
constexpr int NC             = SEGS * CHUNKS_PER_SEG; // 192

// ---------------------------------------------------------------------------
// Device scratch (static __device__ globals only — no runtime allocation)
// ---------------------------------------------------------------------------
__device__ __align__(1024) __nv_bfloat16 g_xhi [(size_t)NTOK * IN];
__device__ __align__(1024) __nv_bfloat16 g_xlo [(size_t)NTOK * IN];
__device__ __align__(1024) __nv_bfloat16 g_whi [(size_t)OUT * IN];
__device__ __align__(1024) __nv_bfloat16 g_wlo [(size_t)OUT * IN];
__device__ __align__(1024) __nv_bfloat16 g_wrhi[(size_t)POOLS * IN];
__device__ __align__(1024) __nv_bfloat16 g_wrlo[(size_t)POOLS * IN];
__device__ __align__(1024) float g_logits[(size_t)NTOK * POOLS];
__device__ float g_dotv[(size_t)NTOK * 2];
__device__ int   g_idxv[(size_t)NTOK * 2];

// ---------------------------------------------------------------------------
// Portable PTX helpers (plain sm_103 target — no tcgen05)
// ---------------------------------------------------------------------------
DINLINE uint32_t smem_u32(const void* p) {
    uint32_t a;
    asm("{ .reg .u64 t; cvta.to.shared.u64 t, %1; cvt.u32.u64 %0, t; }" : "=r"(a) : "l"(p));
    return a;
}

// 128B-row swizzle: 16B-chunk index (bits 4..6) ^= low 3 bits of row (bits 7..9)
#define SWZ128(o) ((o) ^ (((o) >> 3) & 0x70))

#define CP_ASYNC16(saddr, gptr) \
    asm volatile("cp.async.cg.shared.global [%0], [%1], 16;" :: "r"(saddr), "l"(gptr))
#define CP_COMMIT() asm volatile("cp.async.commit_group;" ::: "memory")

template <int N>
DINLINE void cp_wait() { asm volatile("cp.async.wait_group %0;" :: "n"(N) : "memory"); }

DINLINE void ldsm_x4(uint32_t* r, uint32_t addr) {
    asm volatile("ldmatrix.sync.aligned.m8n8.x4.shared.b16 {%0,%1,%2,%3}, [%4];"
                 : "=r"(r[0]), "=r"(r[1]), "=r"(r[2]), "=r"(r[3]) : "r"(addr));
}

DINLINE void mma16816(float* d, const uint32_t* a, uint32_t b0, uint32_t b1) {
    asm volatile(
        "mma.sync.aligned.m16n8k16.row.col.f32.bf16.bf16.f32 "
        "{%0,%1,%2,%3}, {%4,%5,%6,%7}, {%8,%9}, {%0,%1,%2,%3};"
        : "+f"(d[0]), "+f"(d[1]), "+f"(d[2]), "+f"(d[3])
        : "r"(a[0]), "r"(a[1]), "r"(a[2]), "r"(a[3]), "r"(b0), "r"(b1));
}

// ---------------------------------------------------------------------------
// Kernel 0: fp32 -> (bf16 hi, bf16 lo) split (vectorized)
// ---------------------------------------------------------------------------
__global__ void split_kernel(const float* __restrict__ src, int which, int n2) {
    __nv_bfloat16* hi = (which == 0) ? g_xhi : (which == 1) ? g_whi : g_wrhi;
    __nv_bfloat16* lo = (which == 0) ? g_xlo : (which == 1) ? g_wlo : g_wrlo;
    int i = blockIdx.x * blockDim.x + threadIdx.x;
    int stride = gridDim.x * blockDim.x;
    const float2* s2 = (const float2*)src;
    __nv_bfloat162* h2 = (__nv_bfloat162*)hi;
    __nv_bfloat162* l2 = (__nv_bfloat162*)lo;
    for (; i < n2; i += stride) {
        float2 v = s2[i];
        __nv_bfloat16 ha = __float2bfloat16(v.x);
        __nv_bfloat16 hb = __float2bfloat16(v.y);
        __nv_bfloat162 h; h.x = ha; h.y = hb;
        __nv_bfloat162 l;
        l.x = __float2bfloat16(v.x - __bfloat162float(ha));
        l.y = __float2bfloat16(v.y - __bfloat162float(hb));
        h2[i] = h;
        l2[i] = l;
    }
}

// ---------------------------------------------------------------------------
// GEMM: out = x @ W^T with split-bf16 (fp32-equivalent accuracy).
//   MAIN=false: router logits (BM=64, BN=128, 8 warps, 4 stages)
//   MAIN=true : main GEMM + bias + rank-one epilogue
//               (BM=128, BN=256, 16 warps = 4m x 4n, warp tile 32x64, 3 stages)
// cp.async pipeline with one barrier per k-chunk; ldmatrix + mma.sync HMMA.
// ---------------------------------------------------------------------------
template <int TBM, int TBN, int WMN, int WNN, int NSTG, bool MAIN>
__global__ void __launch_bounds__(WMN * WNN * 32, 1)
gemm_kernel(const float* __restrict__ b0v, const float* __restrict__ u,
            float* __restrict__ out) {
    constexpr int NTH = WMN * WNN * 32;
    constexpr int WM  = TBM / WMN;        // warp tile m
    constexpr int WN  = TBN / WNN;        // warp tile n
    constexpr int MT  = WM / 16;
    constexpr int NT2 = WN / 16;
    constexpr int NT8 = WN / 8;
    constexpr int A_B = TBM * 128;
    constexpr int B_B = TBN * 128;
    constexpr int STG = A_B + B_B;

    extern __shared__ __align__(1024) char smem[];
    const uint32_t smem_base = smem_u32(smem);

    const int tid    = threadIdx.x;
    const int wid    = tid >> 5;
    const int lane   = tid & 31;
    const int warp_m = wid % WMN;
    const int warp_n = wid / WMN;

    // group-swizzled CTA rasterization (L2 reuse)
    constexpr int GM = 16;
    const int num_n = MAIN ? (OUT / TBN) : 1;
    const int per_group = GM * num_n;
    const int id = blockIdx.x;
    const int m_tile = (id / per_group) * GM + (id % per_group) % GM;
    const int n_tile = (id % per_group) / GM;
    const int m0 = m_tile * TBM;
    const int n0 = n_tile * TBN;

    const __nv_bfloat16* Aseg[SEGS] = {g_xhi, g_xhi, g_xlo};
    const __nv_bfloat16* Bseg[SEGS];
    if (MAIN) { Bseg[0] = g_whi;  Bseg[1] = g_wlo;  Bseg[2] = g_whi;  }
    else      { Bseg[0] = g_wrhi; Bseg[1] = g_wrlo; Bseg[2] = g_wrhi; }

    auto load_chunk = [&](int chunk, int stage) {
        const int seg = chunk >> 6;          // / CHUNKS_PER_SEG
        const int kc  = chunk & 63;
        const __nv_bfloat16* Ap = Aseg[seg] + (size_t)m0 * IN + kc * BK;
        const __nv_bfloat16* Bp = Bseg[seg] + (size_t)n0 * IN + kc * BK;
        const uint32_t sA = smem_base + stage * STG;
        const uint32_t sB = sA + A_B;
#pragma unroll
        for (int it = 0; it < (TBM * 8) / NTH; it++) {
            int s = tid + it * NTH;
            int row = s >> 3, c = s & 7;
            CP_ASYNC16(sA + SWZ128((uint32_t)(row * 128 + c * 16)),
                       (const void*)(Ap + (size_t)row * IN + c * 8));
        }
#pragma unroll
        for (int it = 0; it < (TBN * 8) / NTH; it++) {
            int s = tid + it * NTH;
            int row = s >> 3, c = s & 7;
            CP_ASYNC16(sB + SWZ128((uint32_t)(row * 128 + c * 16)),
                       (const void*)(Bp + (size_t)row * IN + c * 8));
        }
    };

    // ldmatrix per-thread addressing
    const int xorv = lane & 7;
    const int a_hi = lane >> 4;
    const int b_hi = (lane >> 3) & 1;
    uint32_t a_row[MT], b_row[NT2];
#pragma unroll
    for (int mt = 0; mt < MT; mt++)
        a_row[mt] = (uint32_t)((warp_m * WM + mt * 16 + (lane & 15)) * 128);
#pragma unroll
    for (int nt2 = 0; nt2 < NT2; nt2++)
        b_row[nt2] = (uint32_t)(A_B +
                     (warp_n * WN + nt2 * 16 + ((lane & 7) | ((lane & 16) >> 1))) * 128);

    float acc[MT][NT8][4] = {};

    // prologue: stages 0..NSTG-2
#pragma unroll
    for (int s = 0; s < NSTG - 1; s++) { load_chunk(s, s); CP_COMMIT(); }

    for (int i = 0; i < NC; i++) {
        cp_wait<NSTG - 2>();     // chunk i resident (own-thread copies)
        __syncthreads();         // visibility + all warps done with chunk i-1

        const uint32_t sbase = smem_base + (i % NSTG) * STG;
#pragma unroll
        for (int ks = 0; ks < 4; ks++) {
            uint32_t af[MT][4], bf[NT2][4];
            const uint32_t achunk = (uint32_t)((ks * 2 + a_hi) ^ xorv) << 4;
            const uint32_t bchunk = (uint32_t)((ks * 2 + b_hi) ^ xorv) << 4;
#pragma unroll
            for (int mt = 0; mt < MT; mt++)
                ldsm_x4(af[mt], sbase + a_row[mt] + achunk);
#pragma unroll
            for (int nt2 = 0; nt2 < NT2; nt2++)
                ldsm_x4(bf[nt2], sbase + b_row[nt2] + bchunk);
#pragma unroll
            for (int mt = 0; mt < MT; mt++)
#pragma unroll
                for (int nt2 = 0; nt2 < NT2; nt2++) {
                    mma16816(acc[mt][nt2 * 2 + 0], af[mt], bf[nt2][0], bf[nt2][1]);
                    mma16816(acc[mt][nt2 * 2 + 1], af[mt], bf[nt2][2], bf[nt2][3]);
                }
        }

        // prefetch next chunk into the stage all warps just finished with
        const int nxt = i + NSTG - 1;
        if (nxt < NC) load_chunk(nxt, nxt % NSTG);
        CP_COMMIT();
    }

    // ---------------- epilogue (C frag: rows qrow,+8; cols qcol,+1) ---------
    const int qrow = lane >> 2;
    const int qcol = (lane & 3) * 2;

    if (MAIN) {
        // stage u[n0 .. n0+TBN) x POOLS into smem (padded stride 132 words)
        __syncthreads();         // mainloop smem reads fully drained
        float* us = (float*)smem;
        constexpr int USTR = 132;
#pragma unroll 4
        for (int idx = tid; idx < TBN * (POOLS / 4); idx += NTH) {
            int o  = idx >> 5;           // 32 float4 per row
            int p4 = idx & 31;
            float4 v = *(const float4*)(u + (size_t)(n0 + o) * POOLS + p4 * 4);
            *(float4*)(us + o * USTR + p4 * 4) = v;
        }
        __syncthreads();

        float bo[NT8][2];
#pragma unroll
        for (int nt = 0; nt < NT8; nt++) {
            int o = n0 + warp_n * WN + nt * 8 + qcol;
            bo[nt][0] = b0v[o];
            bo[nt][1] = b0v[o + 1];
        }
#pragma unroll
        for (int mt = 0; mt < MT; mt++)
#pragma unroll
            for (int g = 0; g < 2; g++) {
                const int ntok = m0 + warp_m * WM + mt * 16 + g * 8 + qrow;
                const float d0 = g_dotv[2 * ntok], d1 = g_dotv[2 * ntok + 1];
                const int   p0 = g_idxv[2 * ntok], p1 = g_idxv[2 * ntok + 1];
#pragma unroll
                for (int nt = 0; nt < NT8; nt++) {
                    const int ol = warp_n * WN + nt * 8 + qcol;
                    float v0 = acc[mt][nt][g * 2 + 0] + bo[nt][0]
                             + d0 * us[ol * USTR + p0]
                             + d1 * us[ol * USTR + p1];
                    float v1 = acc[mt][nt][g * 2 + 1] + bo[nt][1]
                             + d0 * us[(ol + 1) * USTR + p0]
                             + d1 * us[(ol + 1) * USTR + p1];
                    *(float2*)(out + (size_t)ntok * OUT + n0 + ol) = make_float2(v0, v1);
                }
            }
    } else {
#pragma unroll
        for (int mt = 0; mt < MT; mt++)
#pragma unroll
            for (int g = 0; g < 2; g++) {
                const int ntok = m0 + warp_m * WM + mt * 16 + g * 8 + qrow;
#pragma unroll
                for (int nt = 0; nt < NT8; nt++) {
                    const int o = warp_n * WN + nt * 8 + qcol;
                    *(float2*)(g_logits + (size_t)ntok * POOLS + o) =
                        make_float2(acc[mt][nt][g * 2 + 0], acc[mt][nt][g * 2 + 1]);
                }
            }
    }
}

// ---------------------------------------------------------------------------
// Kernel 2: fp32 top-2 over logits + dot(x, svh[idx])  (exact fp32)
// (only the top-2 *set* matters: vals are unused; expert sum is symmetric)
// ---------------------------------------------------------------------------
__global__ void __launch_bounds__(128)
topk_kernel(const float* __restrict__ x, const float* __restrict__ svh) {
    const int n = blockIdx.x;
    const int tid = threadIdx.x;
    __shared__ float lg[POOLS];
    __shared__ int sp[2];
    __shared__ float red[2][128];

    lg[tid] = g_logits[(size_t)n * POOLS + tid];
    __syncthreads();

    if (tid == 0) {
        float bv0 = lg[0]; int bi0 = 0;
        float bv1 = -3.402823466e38f; int bi1 = 0;
        for (int t = 1; t < POOLS; t++) {
            float v = lg[t];
            if (v > bv0)      { bv1 = bv0; bi1 = bi0; bv0 = v; bi0 = t; }
            else if (v > bv1) { bv1 = v;  bi1 = t; }
        }
        sp[0] = bi0; sp[1] = bi1;
    }
    __syncthreads();

    const int p0 = sp[0], p1 = sp[1];
    const float4* xr = (const float4*)(x   + (size_t)n  * IN);
    const float4* s0 = (const float4*)(svh + (size_t)p0 * IN);
    const float4* s1 = (const float4*)(svh + (size_t)p1 * IN);
    float a0 = 0.f, a1 = 0.f;
    for (int i = tid; i < IN / 4; i += 128) {
        float4 xv = xr[i], v0 = s0[i], v1 = s1[i];
        a0 += xv.x * v0.x + xv.y * v0.y + xv.z * v0.z + xv.w * v0.w;
        a1 += xv.x * v1.x + xv.y * v1.y + xv.z * v1.z + xv.w * v1.w;
    }
    red[0][tid] = a0; red[1][tid] = a1;
    __syncthreads();
    for (int s = 64; s > 0; s >>= 1) {
        if (tid < s) { red[0][tid] += red[0][tid + s]; red[1][tid] += red[1][tid + s]; }
        __syncthreads();
    }
    if (tid == 0) {
        g_dotv[2 * n]     = red[0][0];
        g_dotv[2 * n + 1] = red[1][0];
        g_idxv[2 * n]     = p0;
        g_idxv[2 * n + 1] = p1;
    }
}

// ---------------------------------------------------------------------------
// Launch
// ---------------------------------------------------------------------------
extern "C" void kernel_launch(void* const* d_in, const int* in_sizes, int n_in,
                              void* d_out, int out_size) {
    const float* x   = (const float*)d_in[0];
    const float* w0  = (const float*)d_in[1];
    const float* b0  = (const float*)d_in[2];
    const float* wr  = (const float*)d_in[3];
    const float* u   = (const float*)d_in[4];
    const float* svh = (const float*)d_in[5];
    float* out = (float*)d_out;

    // main: BM=128, BN=256, 16 warps (4x4), 3 stages -> 144 KB smem
    constexpr int SMEM_MAIN = 3 * (128 + 256) * 128;        // 147,456 B
    // router: BM=64, BN=128, 8 warps (2x4), 4 stages -> 96 KB smem
    constexpr int SMEM_RTR  = 4 * (64 + 128) * 128;         //  98,304 B

    static bool attr_done = false;
    if (!attr_done) {
        cudaFuncSetAttribute((const void*)gemm_kernel<128, 256, 4, 4, 3, true>,
                             cudaFuncAttributeMaxDynamicSharedMemorySize, SMEM_MAIN);
        cudaFuncSetAttribute((const void*)gemm_kernel<64, 128, 2, 4, 4, false>,
                             cudaFuncAttributeMaxDynamicSharedMemorySize, SMEM_RTR);
        attr_done = true;
    }

    // 0) fp32 -> bf16 hi/lo split (vectorized, float2 granularity)
    split_kernel<<<1024, 256>>>(x,  0, NTOK * IN / 2);
    split_kernel<<<512,  256>>>(w0, 1, OUT * IN / 2);
    split_kernel<<<64,   256>>>(wr, 2, POOLS * IN / 2);

    // 1) router logits = x @ wr^T  (128 CTAs)
    gemm_kernel<64, 128, 2, 4, 4, false>
        <<<NTOK / 64, 256, SMEM_RTR>>>(nullptr, nullptr, nullptr);

    // 2) exact fp32 top-2 + dot(x, svh[idx])
    topk_kernel<<<NTOK, 128>>>(x, svh);

    // 3) main GEMM + fused bias + rank-one epilogue (16 warps/CTA)
    gemm_kernel<128, 256, 4, 4, 3, true>
        <<<(NTOK / 128) * (OUT / 256), 512, SMEM_MAIN>>>(b0, u, out);
}

// round 8
// speedup vs baseline: 1.1662x; 1.1662x over previous
#include <cuda_runtime.h>
#include <cuda_bf16.h>
#include <cstdint>

#define DINLINE __device__ __forceinline__

// ---------------------------------------------------------------------------
// Problem constants
// ---------------------------------------------------------------------------
constexpr int NTOK  = 8192;   // B*S tokens
constexpr int IN    = 4096;
constexpr int OUT   = 4096;
constexpr int POOLS = 128;
constexpr int SEGS  = 3;      // bf16 split: xh*wh + xh*wl + xl*wh

constexpr int BK = 64;        // bf16 per k-chunk -> 128B rows
constexpr int CHUNKS_PER_SEG = IN / BK;               // 64
constexpr int NC             = SEGS * CHUNKS_PER_SEG; // 192

// ---------------------------------------------------------------------------
// Device scratch (static __device__ globals only — no runtime allocation)
// ---------------------------------------------------------------------------
__device__ __align__(1024) __nv_bfloat16 g_xhi [(size_t)NTOK * IN];
__device__ __align__(1024) __nv_bfloat16 g_xlo [(size_t)NTOK * IN];
__device__ __align__(1024) __nv_bfloat16 g_whi [(size_t)OUT * IN];
__device__ __align__(1024) __nv_bfloat16 g_wlo [(size_t)OUT * IN];
__device__ __align__(1024) __nv_bfloat16 g_wrhi[(size_t)POOLS * IN];
__device__ __align__(1024) __nv_bfloat16 g_wrlo[(size_t)POOLS * IN];
__device__ __align__(1024) float g_logits[(size_t)NTOK * POOLS];
__device__ float g_dotv[(size_t)NTOK * 2];
__device__ int   g_idxv[(size_t)NTOK * 2];

// ---------------------------------------------------------------------------
// Portable PTX helpers (plain sm_103 target — no tcgen05)
// ---------------------------------------------------------------------------
DINLINE uint32_t smem_u32(const void* p) {
    uint32_t a;
    asm("{ .reg .u64 t; cvta.to.shared.u64 t, %1; cvt.u32.u64 %0, t; }" : "=r"(a) : "l"(p));
    return a;
}

// 128B-row swizzle: 16B-chunk index (bits 4..6) ^= low 3 bits of row (bits 7..9)
#define SWZ128(o) ((o) ^ (((o) >> 3) & 0x70))

#define CP_ASYNC16(saddr, gptr) \
    asm volatile("cp.async.cg.shared.global [%0], [%1], 16;" :: "r"(saddr), "l"(gptr))
#define CP_COMMIT() asm volatile("cp.async.commit_group;" ::: "memory")

template <int N>
DINLINE void cp_wait() { asm volatile("cp.async.wait_group %0;" :: "n"(N) : "memory"); }

DINLINE void ldsm_x4(uint32_t* r, uint32_t addr) {
    asm volatile("ldmatrix.sync.aligned.m8n8.x4.shared.b16 {%0,%1,%2,%3}, [%4];"
                 : "=r"(r[0]), "=r"(r[1]), "=r"(r[2]), "=r"(r[3]) : "r"(addr));
}

DINLINE void mma16816(float* d, const uint32_t* a, uint32_t b0, uint32_t b1) {
    asm volatile(
        "mma.sync.aligned.m16n8k16.row.col.f32.bf16.bf16.f32 "
        "{%0,%1,%2,%3}, {%4,%5,%6,%7}, {%8,%9}, {%0,%1,%2,%3};"
        : "+f"(d[0]), "+f"(d[1]), "+f"(d[2]), "+f"(d[3])
        : "r"(a[0]), "r"(a[1]), "r"(a[2]), "r"(a[3]), "r"(b0), "r"(b1));
}

// ---------------------------------------------------------------------------
// Kernel 0: fp32 -> (bf16 hi, bf16 lo) split (vectorized)
// ---------------------------------------------------------------------------
__global__ void split_kernel(const float* __restrict__ src, int which, int n2) {
    __nv_bfloat16* hi = (which == 0) ? g_xhi : (which == 1) ? g_whi : g_wrhi;
    __nv_bfloat16* lo = (which == 0) ? g_xlo : (which == 1) ? g_wlo : g_wrlo;
    int i = blockIdx.x * blockDim.x + threadIdx.x;
    int stride = gridDim.x * blockDim.x;
    const float2* s2 = (const float2*)src;
    __nv_bfloat162* h2 = (__nv_bfloat162*)hi;
    __nv_bfloat162* l2 = (__nv_bfloat162*)lo;
    for (; i < n2; i += stride) {
        float2 v = s2[i];
        __nv_bfloat16 ha = __float2bfloat16(v.x);
        __nv_bfloat16 hb = __float2bfloat16(v.y);
        __nv_bfloat162 h; h.x = ha; h.y = hb;
        __nv_bfloat162 l;
        l.x = __float2bfloat16(v.x - __bfloat162float(ha));
        l.y = __float2bfloat16(v.y - __bfloat162float(hb));
        h2[i] = h;
        l2[i] = l;
    }
}

// ---------------------------------------------------------------------------
// GEMM: out = x @ W^T with split-bf16 (fp32-equivalent accuracy).
//   MAIN=false: router logits (BM=64, BN=128)
//   MAIN=true : main GEMM + bias + rank-one epilogue (BM=128, BN=256)
// 8 warps = 2(m) x 4(n), warp tile (BM/2) x (BN/4)  [traffic-optimal split].
// cp.async NSTG-stage pipeline with TWO chunks resident (wait_group NSTG-3),
// and ks-level fragment double-buffering with cross-chunk lookahead:
// ldsm for step s+1 issues before the mma block of step s, so the tensor
// pipe never sits on a dependent LDSM chain.
// ---------------------------------------------------------------------------
template <int TBM, int TBN, int NSTG, bool MAIN>
__global__ void __launch_bounds__(256, 1)
gemm_kernel(const float* __restrict__ b0v, const float* __restrict__ u,
            float* __restrict__ out) {
    static_assert(NSTG >= 3, "need two chunks resident");
    constexpr int NTH = 256;
    constexpr int WMN = 2, WNN = 4;
    constexpr int WM  = TBM / WMN;
    constexpr int WN  = TBN / WNN;
    constexpr int MT  = WM / 16;
    constexpr int NT2 = WN / 16;
    constexpr int NT8 = WN / 8;
    constexpr int A_B = TBM * 128;
    constexpr int B_B = TBN * 128;
    constexpr int STG = A_B + B_B;

    extern __shared__ __align__(1024) char smem[];
    const uint32_t smem_base = smem_u32(smem);

    const int tid    = threadIdx.x;
    const int wid    = tid >> 5;
    const int lane   = tid & 31;
    const int warp_m = wid & 1;
    const int warp_n = wid >> 1;

    // group-swizzled CTA rasterization (L2 reuse)
    constexpr int GM = 16;
    const int num_n = MAIN ? (OUT / TBN) : 1;
    const int per_group = GM * num_n;
    const int id = blockIdx.x;
    const int m_tile = (id / per_group) * GM + (id % per_group) % GM;
    const int n_tile = (id % per_group) / GM;
    const int m0 = m_tile * TBM;
    const int n0 = n_tile * TBN;

    const __nv_bfloat16* Aseg[SEGS] = {g_xhi, g_xhi, g_xlo};
    const __nv_bfloat16* Bseg[SEGS];
    if (MAIN) { Bseg[0] = g_whi;  Bseg[1] = g_wlo;  Bseg[2] = g_whi;  }
    else      { Bseg[0] = g_wrhi; Bseg[1] = g_wrlo; Bseg[2] = g_wrhi; }

    auto load_chunk = [&](int chunk, int stage) {
        const int seg = chunk >> 6;          // / CHUNKS_PER_SEG
        const int kc  = chunk & 63;
        const __nv_bfloat16* Ap = Aseg[seg] + (size_t)m0 * IN + kc * BK;
        const __nv_bfloat16* Bp = Bseg[seg] + (size_t)n0 * IN + kc * BK;
        const uint32_t sA = smem_base + stage * STG;
        const uint32_t sB = sA + A_B;
#pragma unroll
        for (int it = 0; it < (TBM * 8) / NTH; it++) {
            int s = tid + it * NTH;
            int row = s >> 3, c = s & 7;
            CP_ASYNC16(sA + SWZ128((uint32_t)(row * 128 + c * 16)),
                       (const void*)(Ap + (size_t)row * IN + c * 8));
        }
#pragma unroll
        for (int it = 0; it < (TBN * 8) / NTH; it++) {
            int s = tid + it * NTH;
            int row = s >> 3, c = s & 7;
            CP_ASYNC16(sB + SWZ128((uint32_t)(row * 128 + c * 16)),
                       (const void*)(Bp + (size_t)row * IN + c * 8));
        }
    };

    // ldmatrix per-thread addressing
    const int xorv = lane & 7;
    const int a_hi = lane >> 4;
    const int b_hi = (lane >> 3) & 1;
    uint32_t a_row[MT], b_row[NT2];
#pragma unroll
    for (int mt = 0; mt < MT; mt++)
        a_row[mt] = (uint32_t)((warp_m * WM + mt * 16 + (lane & 15)) * 128);
#pragma unroll
    for (int nt2 = 0; nt2 < NT2; nt2++)
        b_row[nt2] = (uint32_t)(A_B +
                     (warp_n * WN + nt2 * 16 + ((lane & 7) | ((lane & 16) >> 1))) * 128);

    auto ldfrags = [&](uint32_t sbase, int ks, uint32_t (*af)[4], uint32_t (*bf)[4]) {
        const uint32_t ach = (uint32_t)((ks * 2 + a_hi) ^ xorv) << 4;
        const uint32_t bch = (uint32_t)((ks * 2 + b_hi) ^ xorv) << 4;
#pragma unroll
        for (int mt = 0; mt < MT; mt++)
            ldsm_x4(af[mt], sbase + a_row[mt] + ach);
#pragma unroll
        for (int nt2 = 0; nt2 < NT2; nt2++)
            ldsm_x4(bf[nt2], sbase + b_row[nt2] + bch);
    };

    float acc[MT][NT8][4] = {};

    auto mma_all = [&](uint32_t (*af)[4], uint32_t (*bf)[4]) {
#pragma unroll
        for (int mt = 0; mt < MT; mt++)
#pragma unroll
            for (int nt2 = 0; nt2 < NT2; nt2++) {
                mma16816(acc[mt][nt2 * 2 + 0], af[mt], bf[nt2][0], bf[nt2][1]);
                mma16816(acc[mt][nt2 * 2 + 1], af[mt], bf[nt2][2], bf[nt2][3]);
            }
    };

    uint32_t afA[MT][4], bfA[NT2][4];   // ping
    uint32_t afB[MT][4], bfB[NT2][4];   // pong

    // prologue: load NSTG-1 chunks; make chunks 0 and 1 resident; preload ks0
#pragma unroll
    for (int s = 0; s < NSTG - 1; s++) { load_chunk(s, s); CP_COMMIT(); }
    cp_wait<NSTG - 3>();
    __syncthreads();
    ldfrags(smem_base, 0, afA, bfA);

    for (int i = 0; i < NC; i++) {
        const int nxt = i + NSTG - 1;
        if (nxt < NC) load_chunk(nxt, nxt % NSTG);
        CP_COMMIT();

        const uint32_t sb_i = smem_base + (i % NSTG) * STG;
        const uint32_t sb_n = smem_base + ((i + 1) % NSTG) * STG;

        // ks0: cur=A; prefetch ks1 -> B
        ldfrags(sb_i, 1, afB, bfB);
        mma_all(afA, bfA);
        // ks1: cur=B; prefetch ks2 -> A
        ldfrags(sb_i, 2, afA, bfA);
        mma_all(afB, bfB);
        // ks2: cur=A; prefetch ks3 -> B
        ldfrags(sb_i, 3, afB, bfB);
        mma_all(afA, bfA);
        // ks3: cur=B; prefetch next chunk's ks0 -> A (stale-safe on last iter)
        ldfrags(sb_n, 0, afA, bfA);
        mma_all(afB, bfB);

        // chunk i+2 resident; publish; safe to overwrite stage i next iter
        cp_wait<NSTG - 3>();
        __syncthreads();
    }

    // ---------------- epilogue (C frag: rows qrow,+8; cols qcol,+1) ---------
    const int qrow = lane >> 2;
    const int qcol = (lane & 3) * 2;

    if (MAIN) {
        // stage u[n0 .. n0+TBN) x POOLS into smem (padded stride 132 words)
        float* us = (float*)smem;
        constexpr int USTR = 132;
#pragma unroll 4
        for (int idx = tid; idx < TBN * (POOLS / 4); idx += NTH) {
            int o  = idx >> 5;           // 32 float4 per row
            int p4 = idx & 31;
            float4 v = *(const float4*)(u + (size_t)(n0 + o) * POOLS + p4 * 4);
            *(float4*)(us + o * USTR + p4 * 4) = v;
        }
        __syncthreads();

        float bo[NT8][2];
#pragma unroll
        for (int nt = 0; nt < NT8; nt++) {
            int o = n0 + warp_n * WN + nt * 8 + qcol;
            bo[nt][0] = b0v[o];
            bo[nt][1] = b0v[o + 1];
        }
#pragma unroll
        for (int mt = 0; mt < MT; mt++)
#pragma unroll
            for (int g = 0; g < 2; g++) {
                const int ntok = m0 + warp_m * WM + mt * 16 + g * 8 + qrow;
                const float d0 = g_dotv[2 * ntok], d1 = g_dotv[2 * ntok + 1];
                const int   p0 = g_idxv[2 * ntok], p1 = g_idxv[2 * ntok + 1];
#pragma unroll
                for (int nt = 0; nt < NT8; nt++) {
                    const int ol = warp_n * WN + nt * 8 + qcol;
                    float v0 = acc[mt][nt][g * 2 + 0] + bo[nt][0]
                             + d0 * us[ol * USTR + p0]
                             + d1 * us[ol * USTR + p1];
                    float v1 = acc[mt][nt][g * 2 + 1] + bo[nt][1]
                             + d0 * us[(ol + 1) * USTR + p0]
                             + d1 * us[(ol + 1) * USTR + p1];
                    *(float2*)(out + (size_t)ntok * OUT + n0 + ol) = make_float2(v0, v1);
                }
            }
    } else {
#pragma unroll
        for (int mt = 0; mt < MT; mt++)
#pragma unroll
            for (int g = 0; g < 2; g++) {
                const int ntok = m0 + warp_m * WM + mt * 16 + g * 8 + qrow;
#pragma unroll
                for (int nt = 0; nt < NT8; nt++) {
                    const int o = warp_n * WN + nt * 8 + qcol;
                    *(float2*)(g_logits + (size_t)ntok * POOLS + o) =
                        make_float2(acc[mt][nt][g * 2 + 0], acc[mt][nt][g * 2 + 1]);
                }
            }
    }
}

// ---------------------------------------------------------------------------
// Kernel 2: fp32 top-2 over logits + dot(x, svh[idx])  (exact fp32)
// (only the top-2 *set* matters: vals are unused; expert sum is symmetric)
// ---------------------------------------------------------------------------
__global__ void __launch_bounds__(128)
topk_kernel(const float* __restrict__ x, const float* __restrict__ svh) {
    const int n = blockIdx.x;
    const int tid = threadIdx.x;
    __shared__ float lg[POOLS];
    __shared__ int sp[2];
    __shared__ float red[2][128];

    lg[tid] = g_logits[(size_t)n * POOLS + tid];
    __syncthreads();

    if (tid == 0) {
        float bv0 = lg[0]; int bi0 = 0;
        float bv1 = -3.402823466e38f; int bi1 = 0;
        for (int t = 1; t < POOLS; t++) {
            float v = lg[t];
            if (v > bv0)      { bv1 = bv0; bi1 = bi0; bv0 = v; bi0 = t; }
            else if (v > bv1) { bv1 = v;  bi1 = t; }
        }
        sp[0] = bi0; sp[1] = bi1;
    }
    __syncthreads();

    const int p0 = sp[0], p1 = sp[1];
    const float4* xr = (const float4*)(x   + (size_t)n  * IN);
    const float4* s0 = (const float4*)(svh + (size_t)p0 * IN);
    const float4* s1 = (const float4*)(svh + (size_t)p1 * IN);
    float a0 = 0.f, a1 = 0.f;
    for (int i = tid; i < IN / 4; i += 128) {
        float4 xv = xr[i], v0 = s0[i], v1 = s1[i];
        a0 += xv.x * v0.x + xv.y * v0.y + xv.z * v0.z + xv.w * v0.w;
        a1 += xv.x * v1.x + xv.y * v1.y + xv.z * v1.z + xv.w * v1.w;
    }
    red[0][tid] = a0; red[1][tid] = a1;
    __syncthreads();
    for (int s = 64; s > 0; s >>= 1) {
        if (tid < s) { red[0][tid] += red[0][tid + s]; red[1][tid] += red[1][tid + s]; }
        __syncthreads();
    }
    if (tid == 0) {
        g_dotv[2 * n]     = red[0][0];
        g_dotv[2 * n + 1] = red[1][0];
        g_idxv[2 * n]     = p0;
        g_idxv[2 * n + 1] = p1;
    }
}

// ---------------------------------------------------------------------------
// Launch
// ---------------------------------------------------------------------------
extern "C" void kernel_launch(void* const* d_in, const int* in_sizes, int n_in,
                              void* d_out, int out_size) {
    const float* x   = (const float*)d_in[0];
    const float* w0  = (const float*)d_in[1];
    const float* b0  = (const float*)d_in[2];
    const float* wr  = (const float*)d_in[3];
    const float* u   = (const float*)d_in[4];
    const float* svh = (const float*)d_in[5];
    float* out = (float*)d_out;

    // main: BM=128, BN=256, 8 warps, 4 stages -> 192 KB smem
    constexpr int SMEM_MAIN = 4 * (128 + 256) * 128;        // 196,608 B
    // router: BM=64, BN=128, 8 warps, 4 stages -> 96 KB smem
    constexpr int SMEM_RTR  = 4 * (64 + 128) * 128;         //  98,304 B

    cudaFuncSetAttribute((const void*)gemm_kernel<128, 256, 4, true>,
                         cudaFuncAttributeMaxDynamicSharedMemorySize, SMEM_MAIN);
    cudaFuncSetAttribute((const void*)gemm_kernel<64, 128, 4, false>,
                         cudaFuncAttributeMaxDynamicSharedMemorySize, SMEM_RTR);

    // 0) fp32 -> bf16 hi/lo split (vectorized, float2 granularity)
    split_kernel<<<1024, 256>>>(x,  0, NTOK * IN / 2);
    split_kernel<<<512,  256>>>(w0, 1, OUT * IN / 2);
    split_kernel<<<64,   256>>>(wr, 2, POOLS * IN / 2);

    // 1) router logits = x @ wr^T  (128 CTAs)
    gemm_kernel<64, 128, 4, false>
        <<<NTOK / 64, 256, SMEM_RTR>>>(nullptr, nullptr, nullptr);

    // 2) exact fp32 top-2 + dot(x, svh[idx])
    topk_kernel<<<NTOK, 128>>>(x, svh);

    // 3) main GEMM + fused bias + rank-one epilogue
    gemm_kernel<128, 256, 4, true>
        <<<(NTOK / 128) * (OUT / 256), 256, SMEM_MAIN>>>(b0, u, out);
}

// round 9
// speedup vs baseline: 1.5908x; 1.3641x over previous
#include <cuda_runtime.h>
#include <cuda_bf16.h>
#include <cuda_fp16.h>
#include <cstdint>

#define DINLINE __device__ __forceinline__

// ---------------------------------------------------------------------------
// Problem constants
// ---------------------------------------------------------------------------
constexpr int NTOK  = 8192;   // B*S tokens
constexpr int IN    = 4096;
constexpr int OUT   = 4096;
constexpr int POOLS = 128;

constexpr int BK = 64;        // 16-bit elems per k-chunk -> 128B rows

constexpr float WSCALE    = 1024.0f;   // w0 prescale so wl is fp16-normal
constexpr float INV_WSCALE = 1.0f / 1024.0f;

// ---------------------------------------------------------------------------
// Device scratch (static __device__ globals only — no runtime allocation)
// ---------------------------------------------------------------------------
__device__ __align__(1024) __nv_bfloat16 g_xhi [(size_t)NTOK * IN];   // router A hi
__device__ __align__(1024) __nv_bfloat16 g_xlo [(size_t)NTOK * IN];   // router A lo
__device__ __align__(1024) __half        g_xh  [(size_t)NTOK * IN];   // main A (fp16)
__device__ __align__(1024) __half        g_wh  [(size_t)OUT * IN];    // fp16(1024*w0)
__device__ __align__(1024) __half        g_wl  [(size_t)OUT * IN];    // residual
__device__ __align__(1024) __nv_bfloat16 g_wrhi[(size_t)POOLS * IN];
__device__ __align__(1024) __nv_bfloat16 g_wrlo[(size_t)POOLS * IN];
__device__ __align__(1024) float g_logits[(size_t)NTOK * POOLS];
__device__ float g_dotv[(size_t)NTOK * 2];
__device__ int   g_idxv[(size_t)NTOK * 2];

// ---------------------------------------------------------------------------
// Portable PTX helpers (plain sm_103 target — no tcgen05)
// ---------------------------------------------------------------------------
DINLINE uint32_t smem_u32(const void* p) {
    uint32_t a;
    asm("{ .reg .u64 t; cvta.to.shared.u64 t, %1; cvt.u32.u64 %0, t; }" : "=r"(a) : "l"(p));
    return a;
}

// 128B-row swizzle: 16B-chunk index (bits 4..6) ^= low 3 bits of row (bits 7..9)
#define SWZ128(o) ((o) ^ (((o) >> 3) & 0x70))

#define CP_ASYNC16(saddr, gptr) \
    asm volatile("cp.async.cg.shared.global [%0], [%1], 16;" :: "r"(saddr), "l"(gptr))
#define CP_COMMIT() asm volatile("cp.async.commit_group;" ::: "memory")

template <int N>
DINLINE void cp_wait() { asm volatile("cp.async.wait_group %0;" :: "n"(N) : "memory"); }

DINLINE void ldsm_x4(uint32_t* r, uint32_t addr) {
    asm volatile("ldmatrix.sync.aligned.m8n8.x4.shared.b16 {%0,%1,%2,%3}, [%4];"
                 : "=r"(r[0]), "=r"(r[1]), "=r"(r[2]), "=r"(r[3]) : "r"(addr));
}

template <bool FP16>
DINLINE void mma16816(float* d, const uint32_t* a, uint32_t b0, uint32_t b1) {
    if (FP16)
        asm volatile(
            "mma.sync.aligned.m16n8k16.row.col.f32.f16.f16.f32 "
            "{%0,%1,%2,%3}, {%4,%5,%6,%7}, {%8,%9}, {%0,%1,%2,%3};"
            : "+f"(d[0]), "+f"(d[1]), "+f"(d[2]), "+f"(d[3])
            : "r"(a[0]), "r"(a[1]), "r"(a[2]), "r"(a[3]), "r"(b0), "r"(b1));
    else
        asm volatile(
            "mma.sync.aligned.m16n8k16.row.col.f32.bf16.bf16.f32 "
            "{%0,%1,%2,%3}, {%4,%5,%6,%7}, {%8,%9}, {%0,%1,%2,%3};"
            : "+f"(d[0]), "+f"(d[1]), "+f"(d[2]), "+f"(d[3])
            : "r"(a[0]), "r"(a[1]), "r"(a[2]), "r"(a[3]), "r"(b0), "r"(b1));
}

// ---------------------------------------------------------------------------
// Kernel 0a: x -> bf16 hi/lo (router) + fp16 (main), vectorized
// ---------------------------------------------------------------------------
__global__ void split_x_kernel(const float* __restrict__ src, int n2) {
    int i = blockIdx.x * blockDim.x + threadIdx.x;
    int stride = gridDim.x * blockDim.x;
    const float2* s2 = (const float2*)src;
    __nv_bfloat162* h2 = (__nv_bfloat162*)g_xhi;
    __nv_bfloat162* l2 = (__nv_bfloat162*)g_xlo;
    __half2* f2 = (__half2*)g_xh;
    for (; i < n2; i += stride) {
        float2 v = s2[i];
        __nv_bfloat16 ha = __float2bfloat16(v.x);
        __nv_bfloat16 hb = __float2bfloat16(v.y);
        __nv_bfloat162 h; h.x = ha; h.y = hb;
        __nv_bfloat162 l;
        l.x = __float2bfloat16(v.x - __bfloat162float(ha));
        l.y = __float2bfloat16(v.y - __bfloat162float(hb));
        h2[i] = h;
        l2[i] = l;
        f2[i] = __floats2half2_rn(v.x, v.y);
    }
}

// Kernel 0b: w0 -> fp16 hi/lo of (WSCALE * w0)
__global__ void split_w_kernel(const float* __restrict__ src, int n2) {
    int i = blockIdx.x * blockDim.x + threadIdx.x;
    int stride = gridDim.x * blockDim.x;
    const float2* s2 = (const float2*)src;
    __half2* h2 = (__half2*)g_wh;
    __half2* l2 = (__half2*)g_wl;
    for (; i < n2; i += stride) {
        float2 v = s2[i];
        float sx = v.x * WSCALE, sy = v.y * WSCALE;
        __half ha = __float2half_rn(sx);
        __half hb = __float2half_rn(sy);
        __half2 h; h.x = ha; h.y = hb;
        __half2 l;
        l.x = __float2half_rn(sx - __half2float(ha));
        l.y = __float2half_rn(sy - __half2float(hb));
        h2[i] = h;
        l2[i] = l;
    }
}

// Kernel 0c: wr -> bf16 hi/lo (router weights; selection-critical precision)
__global__ void split_wr_kernel(const float* __restrict__ src, int n2) {
    int i = blockIdx.x * blockDim.x + threadIdx.x;
    int stride = gridDim.x * blockDim.x;
    const float2* s2 = (const float2*)src;
    __nv_bfloat162* h2 = (__nv_bfloat162*)g_wrhi;
    __nv_bfloat162* l2 = (__nv_bfloat162*)g_wrlo;
    for (; i < n2; i += stride) {
        float2 v = s2[i];
        __nv_bfloat16 ha = __float2bfloat16(v.x);
        __nv_bfloat16 hb = __float2bfloat16(v.y);
        __nv_bfloat162 h; h.x = ha; h.y = hb;
        __nv_bfloat162 l;
        l.x = __float2bfloat16(v.x - __bfloat162float(ha));
        l.y = __float2bfloat16(v.y - __bfloat162float(hb));
        h2[i] = h;
        l2[i] = l;
    }
}

// ---------------------------------------------------------------------------
// GEMM: out = x @ W^T.
//   MAIN=false: router logits, 3-term bf16 split (selection-exact):
//               xh*wrh + xh*wrl + xl*wrh                     (BM=64, BN=128)
//   MAIN=true : main GEMM, 2-term fp16 split (w prescaled):
//               xh*wh + xh*wl, then *1/1024 + b0 + rank-one  (BM=128, BN=256)
// 8 warps = 2(m) x 4(n); cp.async 4-stage pipeline, two chunks resident;
// fragment double-buffering with cross-chunk ldsm lookahead.
// ---------------------------------------------------------------------------
template <int TBM, int TBN, int NSTG, bool MAIN>
__global__ void __launch_bounds__(256, 1)
gemm_kernel(const float* __restrict__ b0v, const float* __restrict__ u,
            float* __restrict__ out) {
    static_assert(NSTG >= 3, "need two chunks resident");
    constexpr int NTH = 256;
    constexpr int WMN = 2, WNN = 4;
    constexpr int WM  = TBM / WMN;
    constexpr int WN  = TBN / WNN;
    constexpr int MT  = WM / 16;
    constexpr int NT2 = WN / 16;
    constexpr int NT8 = WN / 8;
    constexpr int A_B = TBM * 128;
    constexpr int B_B = TBN * 128;
    constexpr int STG = A_B + B_B;
    constexpr int NSEG = MAIN ? 2 : 3;
    constexpr int NCH  = NSEG * (IN / BK);    // 128 (main) / 192 (router)

    extern __shared__ __align__(1024) char smem[];
    const uint32_t smem_base = smem_u32(smem);

    const int tid    = threadIdx.x;
    const int wid    = tid >> 5;
    const int lane   = tid & 31;
    const int warp_m = wid & 1;
    const int warp_n = wid >> 1;

    // group-swizzled CTA rasterization (L2 reuse)
    constexpr int GM = 16;
    const int num_n = MAIN ? (OUT / TBN) : 1;
    const int per_group = GM * num_n;
    const int id = blockIdx.x;
    const int m_tile = (id / per_group) * GM + (id % per_group) % GM;
    const int n_tile = (id % per_group) / GM;
    const int m0 = m_tile * TBM;
    const int n0 = n_tile * TBN;

    const void* Aseg[NSEG];
    const void* Bseg[NSEG];
    if (MAIN) {
        Aseg[0] = g_xh;  Aseg[1] = g_xh;
        Bseg[0] = g_wh;  Bseg[1] = g_wl;
    } else {
        Aseg[0] = g_xhi;  Aseg[1] = g_xhi;  Aseg[NSEG - 1] = g_xlo;
        Bseg[0] = g_wrhi; Bseg[1] = g_wrlo; Bseg[NSEG - 1] = g_wrhi;
    }

    auto load_chunk = [&](int chunk, int stage) {
        const int seg = chunk >> 6;          // / (IN/BK)
        const int kc  = chunk & 63;
        const uint16_t* Ap = (const uint16_t*)Aseg[seg] + (size_t)m0 * IN + kc * BK;
        const uint16_t* Bp = (const uint16_t*)Bseg[seg] + (size_t)n0 * IN + kc * BK;
        const uint32_t sA = smem_base + stage * STG;
        const uint32_t sB = sA + A_B;
#pragma unroll
        for (int it = 0; it < (TBM * 8) / NTH; it++) {
            int s = tid + it * NTH;
            int row = s >> 3, c = s & 7;
            CP_ASYNC16(sA + SWZ128((uint32_t)(row * 128 + c * 16)),
                       (const void*)(Ap + (size_t)row * IN + c * 8));
        }
#pragma unroll
        for (int it = 0; it < (TBN * 8) / NTH; it++) {
            int s = tid + it * NTH;
            int row = s >> 3, c = s & 7;
            CP_ASYNC16(sB + SWZ128((uint32_t)(row * 128 + c * 16)),
                       (const void*)(Bp + (size_t)row * IN + c * 8));
        }
    };

    // ldmatrix per-thread addressing
    const int xorv = lane & 7;
    const int a_hi = lane >> 4;
    const int b_hi = (lane >> 3) & 1;
    uint32_t a_row[MT], b_row[NT2];
#pragma unroll
    for (int mt = 0; mt < MT; mt++)
        a_row[mt] = (uint32_t)((warp_m * WM + mt * 16 + (lane & 15)) * 128);
#pragma unroll
    for (int nt2 = 0; nt2 < NT2; nt2++)
        b_row[nt2] = (uint32_t)(A_B +
                     (warp_n * WN + nt2 * 16 + ((lane & 7) | ((lane & 16) >> 1))) * 128);

    auto ldfrags = [&](uint32_t sbase, int ks, uint32_t (*af)[4], uint32_t (*bf)[4]) {
        const uint32_t ach = (uint32_t)((ks * 2 + a_hi) ^ xorv) << 4;
        const uint32_t bch = (uint32_t)((ks * 2 + b_hi) ^ xorv) << 4;
#pragma unroll
        for (int mt = 0; mt < MT; mt++)
            ldsm_x4(af[mt], sbase + a_row[mt] + ach);
#pragma unroll
        for (int nt2 = 0; nt2 < NT2; nt2++)
            ldsm_x4(bf[nt2], sbase + b_row[nt2] + bch);
    };

    float acc[MT][NT8][4] = {};

    auto mma_all = [&](uint32_t (*af)[4], uint32_t (*bf)[4]) {
#pragma unroll
        for (int mt = 0; mt < MT; mt++)
#pragma unroll
            for (int nt2 = 0; nt2 < NT2; nt2++) {
                mma16816<MAIN>(acc[mt][nt2 * 2 + 0], af[mt], bf[nt2][0], bf[nt2][1]);
                mma16816<MAIN>(acc[mt][nt2 * 2 + 1], af[mt], bf[nt2][2], bf[nt2][3]);
            }
    };

    uint32_t afA[MT][4], bfA[NT2][4];   // ping
    uint32_t afB[MT][4], bfB[NT2][4];   // pong

    // prologue: load NSTG-1 chunks; make chunks 0 and 1 resident; preload ks0
#pragma unroll
    for (int s = 0; s < NSTG - 1; s++) { load_chunk(s, s); CP_COMMIT(); }
    cp_wait<NSTG - 3>();
    __syncthreads();
    ldfrags(smem_base, 0, afA, bfA);

    for (int i = 0; i < NCH; i++) {
        const int nxt = i + NSTG - 1;
        if (nxt < NCH) load_chunk(nxt, nxt % NSTG);
        CP_COMMIT();

        const uint32_t sb_i = smem_base + (i % NSTG) * STG;
        const uint32_t sb_n = smem_base + ((i + 1) % NSTG) * STG;

        // ks0: cur=A; prefetch ks1 -> B
        ldfrags(sb_i, 1, afB, bfB);
        mma_all(afA, bfA);
        // ks1: cur=B; prefetch ks2 -> A
        ldfrags(sb_i, 2, afA, bfA);
        mma_all(afB, bfB);
        // ks2: cur=A; prefetch ks3 -> B
        ldfrags(sb_i, 3, afB, bfB);
        mma_all(afA, bfA);
        // ks3: cur=B; prefetch next chunk's ks0 -> A (stale-safe on last iter)
        ldfrags(sb_n, 0, afA, bfA);
        mma_all(afB, bfB);

        // chunk i+2 resident; publish; safe to overwrite stage i next iter
        cp_wait<NSTG - 3>();
        __syncthreads();
    }

    // ---------------- epilogue (C frag: rows qrow,+8; cols qcol,+1) ---------
    const int qrow = lane >> 2;
    const int qcol = (lane & 3) * 2;

    if (MAIN) {
        // stage u[n0 .. n0+TBN) x POOLS into smem (padded stride 132 words)
        float* us = (float*)smem;
        constexpr int USTR = 132;
#pragma unroll 4
        for (int idx = tid; idx < TBN * (POOLS / 4); idx += NTH) {
            int o  = idx >> 5;           // 32 float4 per row
            int p4 = idx & 31;
            float4 v = *(const float4*)(u + (size_t)(n0 + o) * POOLS + p4 * 4);
            *(float4*)(us + o * USTR + p4 * 4) = v;
        }
        __syncthreads();

        float bo[NT8][2];
#pragma unroll
        for (int nt = 0; nt < NT8; nt++) {
            int o = n0 + warp_n * WN + nt * 8 + qcol;
            bo[nt][0] = b0v[o];
            bo[nt][1] = b0v[o + 1];
        }
#pragma unroll
        for (int mt = 0; mt < MT; mt++)
#pragma unroll
            for (int g = 0; g < 2; g++) {
                const int ntok = m0 + warp_m * WM + mt * 16 + g * 8 + qrow;
                const float d0 = g_dotv[2 * ntok], d1 = g_dotv[2 * ntok + 1];
                const int   p0 = g_idxv[2 * ntok], p1 = g_idxv[2 * ntok + 1];
#pragma unroll
                for (int nt = 0; nt < NT8; nt++) {
                    const int ol = warp_n * WN + nt * 8 + qcol;
                    float v0 = acc[mt][nt][g * 2 + 0] * INV_WSCALE + bo[nt][0]
                             + d0 * us[ol * USTR + p0]
                             + d1 * us[ol * USTR + p1];
                    float v1 = acc[mt][nt][g * 2 + 1] * INV_WSCALE + bo[nt][1]
                             + d0 * us[(ol + 1) * USTR + p0]
                             + d1 * us[(ol + 1) * USTR + p1];
                    *(float2*)(out + (size_t)ntok * OUT + n0 + ol) = make_float2(v0, v1);
                }
            }
    } else {
#pragma unroll
        for (int mt = 0; mt < MT; mt++)
#pragma unroll
            for (int g = 0; g < 2; g++) {
                const int ntok = m0 + warp_m * WM + mt * 16 + g * 8 + qrow;
#pragma unroll
                for (int nt = 0; nt < NT8; nt++) {
                    const int o = warp_n * WN + nt * 8 + qcol;
                    *(float2*)(g_logits + (size_t)ntok * POOLS + o) =
                        make_float2(acc[mt][nt][g * 2 + 0], acc[mt][nt][g * 2 + 1]);
                }
            }
    }
}

// ---------------------------------------------------------------------------
// Kernel 2: fp32 top-2 over logits + dot(x, svh[idx])  (exact fp32)
// (only the top-2 *set* matters: vals are unused; expert sum is symmetric)
// ---------------------------------------------------------------------------
__global__ void __launch_bounds__(128)
topk_kernel(const float* __restrict__ x, const float* __restrict__ svh) {
    const int n = blockIdx.x;
    const int tid = threadIdx.x;
    __shared__ float lg[POOLS];
    __shared__ int sp[2];
    __shared__ float red[2][128];

    lg[tid] = g_logits[(size_t)n * POOLS + tid];
    __syncthreads();

    if (tid == 0) {
        float bv0 = lg[0]; int bi0 = 0;
        float bv1 = -3.402823466e38f; int bi1 = 0;
        for (int t = 1; t < POOLS; t++) {
            float v = lg[t];
            if (v > bv0)      { bv1 = bv0; bi1 = bi0; bv0 = v; bi0 = t; }
            else if (v > bv1) { bv1 = v;  bi1 = t; }
        }
        sp[0] = bi0; sp[1] = bi1;
    }
    __syncthreads();

    const int p0 = sp[0], p1 = sp[1];
    const float4* xr = (const float4*)(x   + (size_t)n  * IN);
    const float4* s0 = (const float4*)(svh + (size_t)p0 * IN);
    const float4* s1 = (const float4*)(svh + (size_t)p1 * IN);
    float a0 = 0.f, a1 = 0.f;
    for (int i = tid; i < IN / 4; i += 128) {
        float4 xv = xr[i], v0 = s0[i], v1 = s1[i];
        a0 += xv.x * v0.x + xv.y * v0.y + xv.z * v0.z + xv.w * v0.w;
        a1 += xv.x * v1.x + xv.y * v1.y + xv.z * v1.z + xv.w * v1.w;
    }
    red[0][tid] = a0; red[1][tid] = a1;
    __syncthreads();
    for (int s = 64; s > 0; s >>= 1) {
        if (tid < s) { red[0][tid] += red[0][tid + s]; red[1][tid] += red[1][tid + s]; }
        __syncthreads();
    }
    if (tid == 0) {
        g_dotv[2 * n]     = red[0][0];
        g_dotv[2 * n + 1] = red[1][0];
        g_idxv[2 * n]     = p0;
        g_idxv[2 * n + 1] = p1;
    }
}

// ---------------------------------------------------------------------------
// Launch
// ---------------------------------------------------------------------------
extern "C" void kernel_launch(void* const* d_in, const int* in_sizes, int n_in,
                              void* d_out, int out_size) {
    const float* x   = (const float*)d_in[0];
    const float* w0  = (const float*)d_in[1];
    const float* b0  = (const float*)d_in[2];
    const float* wr  = (const float*)d_in[3];
    const float* u   = (const float*)d_in[4];
    const float* svh = (const float*)d_in[5];
    float* out = (float*)d_out;

    // main: BM=128, BN=256, 8 warps, 4 stages -> 192 KB smem
    constexpr int SMEM_MAIN = 4 * (128 + 256) * 128;        // 196,608 B
    // router: BM=64, BN=128, 8 warps, 4 stages -> 96 KB smem
    constexpr int SMEM_RTR  = 4 * (64 + 128) * 128;         //  98,304 B

    cudaFuncSetAttribute((const void*)gemm_kernel<128, 256, 4, true>,
                         cudaFuncAttributeMaxDynamicSharedMemorySize, SMEM_MAIN);
    cudaFuncSetAttribute((const void*)gemm_kernel<64, 128, 4, false>,
                         cudaFuncAttributeMaxDynamicSharedMemorySize, SMEM_RTR);

    // 0) precision splits
    split_x_kernel <<<1024, 256>>>(x,  NTOK * IN / 2);    // bf16 hi/lo + fp16
    split_w_kernel <<<512,  256>>>(w0, OUT * IN / 2);     // fp16 hi/lo of 1024*w0
    split_wr_kernel<<<64,   256>>>(wr, POOLS * IN / 2);   // bf16 hi/lo

    // 1) router logits = x @ wr^T  (3-term bf16: selection-exact; 128 CTAs)
    gemm_kernel<64, 128, 4, false>
        <<<NTOK / 64, 256, SMEM_RTR>>>(nullptr, nullptr, nullptr);

    // 2) exact fp32 top-2 + dot(x, svh[idx])
    topk_kernel<<<NTOK, 128>>>(x, svh);

    // 3) main GEMM (2-term fp16, w prescaled) + bias + rank-one epilogue
    gemm_kernel<128, 256, 4, true>
        <<<(NTOK / 128) * (OUT / 256), 256, SMEM_MAIN>>>(b0, u, out);
}

// round 10
// speedup vs baseline: 2.6808x; 1.6852x over previous
#include <cuda_runtime.h>
#include <cuda_bf16.h>
#include <cuda_fp16.h>
#include <cstdint>

#define DINLINE __device__ __forceinline__

// ---------------------------------------------------------------------------
// Problem constants
// ---------------------------------------------------------------------------
constexpr int NTOK  = 8192;   // B*S tokens
constexpr int IN    = 4096;
constexpr int OUT   = 4096;
constexpr int POOLS = 128;

constexpr int BK = 64;        // 16-bit elems per k-chunk -> 128B rows

constexpr float WSCALE     = 1024.0f;   // w0 prescale (keeps wl away from subnormals)
constexpr float INV_WSCALE = 1.0f / 1024.0f;

// ---------------------------------------------------------------------------
// Device scratch (static __device__ globals only — no runtime allocation)
// ---------------------------------------------------------------------------
__device__ __align__(1024) __nv_bfloat16 g_xhi [(size_t)NTOK * IN];   // router A hi
__device__ __align__(1024) __nv_bfloat16 g_xlo [(size_t)NTOK * IN];   // router A lo
__device__ __align__(1024) __half        g_xh  [(size_t)NTOK * IN];   // main A (fp16)
__device__ __align__(1024) __half        g_wh  [(size_t)OUT * IN];    // fp16(1024*w0)
__device__ __align__(1024) __nv_bfloat16 g_wrhi[(size_t)POOLS * IN];
__device__ __align__(1024) __nv_bfloat16 g_wrlo[(size_t)POOLS * IN];
__device__ __align__(1024) float g_logits[(size_t)NTOK * POOLS];
__device__ float g_dotv[(size_t)NTOK * 2];
__device__ int   g_idxv[(size_t)NTOK * 2];

// ---------------------------------------------------------------------------
// Portable PTX helpers (plain sm_103 target — no tcgen05)
// ---------------------------------------------------------------------------
DINLINE uint32_t smem_u32(const void* p) {
    uint32_t a;
    asm("{ .reg .u64 t; cvta.to.shared.u64 t, %1; cvt.u32.u64 %0, t; }" : "=r"(a) : "l"(p));
    return a;
}

// 128B-row swizzle: 16B-chunk index (bits 4..6) ^= low 3 bits of row (bits 7..9)
#define SWZ128(o) ((o) ^ (((o) >> 3) & 0x70))

#define CP_ASYNC16(saddr, gptr) \
    asm volatile("cp.async.cg.shared.global [%0], [%1], 16;" :: "r"(saddr), "l"(gptr))
#define CP_COMMIT() asm volatile("cp.async.commit_group;" ::: "memory")

template <int N>
DINLINE void cp_wait() { asm volatile("cp.async.wait_group %0;" :: "n"(N) : "memory"); }

DINLINE void ldsm_x4(uint32_t* r, uint32_t addr) {
    asm volatile("ldmatrix.sync.aligned.m8n8.x4.shared.b16 {%0,%1,%2,%3}, [%4];"
                 : "=r"(r[0]), "=r"(r[1]), "=r"(r[2]), "=r"(r[3]) : "r"(addr));
}

template <bool FP16>
DINLINE void mma16816(float* d, const uint32_t* a, uint32_t b0, uint32_t b1) {
    if (FP16)
        asm volatile(
            "mma.sync.aligned.m16n8k16.row.col.f32.f16.f16.f32 "
            "{%0,%1,%2,%3}, {%4,%5,%6,%7}, {%8,%9}, {%0,%1,%2,%3};"
            : "+f"(d[0]), "+f"(d[1]), "+f"(d[2]), "+f"(d[3])
            : "r"(a[0]), "r"(a[1]), "r"(a[2]), "r"(a[3]), "r"(b0), "r"(b1));
    else
        asm volatile(
            "mma.sync.aligned.m16n8k16.row.col.f32.bf16.bf16.f32 "
            "{%0,%1,%2,%3}, {%4,%5,%6,%7}, {%8,%9}, {%0,%1,%2,%3};"
            : "+f"(d[0]), "+f"(d[1]), "+f"(d[2]), "+f"(d[3])
            : "r"(a[0]), "r"(a[1]), "r"(a[2]), "r"(a[3]), "r"(b0), "r"(b1));
}

// ---------------------------------------------------------------------------
// Kernel 0a: x -> bf16 hi/lo (router) + fp16 (main), vectorized
// ---------------------------------------------------------------------------
__global__ void split_x_kernel(const float* __restrict__ src, int n2) {
    int i = blockIdx.x * blockDim.x + threadIdx.x;
    int stride = gridDim.x * blockDim.x;
    const float2* s2 = (const float2*)src;
    __nv_bfloat162* h2 = (__nv_bfloat162*)g_xhi;
    __nv_bfloat162* l2 = (__nv_bfloat162*)g_xlo;
    __half2* f2 = (__half2*)g_xh;
    for (; i < n2; i += stride) {
        float2 v = s2[i];
        __nv_bfloat16 ha = __float2bfloat16(v.x);
        __nv_bfloat16 hb = __float2bfloat16(v.y);
        __nv_bfloat162 h; h.x = ha; h.y = hb;
        __nv_bfloat162 l;
        l.x = __float2bfloat16(v.x - __bfloat162float(ha));
        l.y = __float2bfloat16(v.y - __bfloat162float(hb));
        h2[i] = h;
        l2[i] = l;
        f2[i] = __floats2half2_rn(v.x, v.y);
    }
}

// Kernel 0b: w0 -> fp16(WSCALE * w0)  (single term)
__global__ void split_w_kernel(const float* __restrict__ src, int n2) {
    int i = blockIdx.x * blockDim.x + threadIdx.x;
    int stride = gridDim.x * blockDim.x;
    const float2* s2 = (const float2*)src;
    __half2* h2 = (__half2*)g_wh;
    for (; i < n2; i += stride) {
        float2 v = s2[i];
        h2[i] = __floats2half2_rn(v.x * WSCALE, v.y * WSCALE);
    }
}

// Kernel 0c: wr -> bf16 hi/lo (router weights; selection-critical precision)
__global__ void split_wr_kernel(const float* __restrict__ src, int n2) {
    int i = blockIdx.x * blockDim.x + threadIdx.x;
    int stride = gridDim.x * blockDim.x;
    const float2* s2 = (const float2*)src;
    __nv_bfloat162* h2 = (__nv_bfloat162*)g_wrhi;
    __nv_bfloat162* l2 = (__nv_bfloat162*)g_wrlo;
    for (; i < n2; i += stride) {
        float2 v = s2[i];
        __nv_bfloat16 ha = __float2bfloat16(v.x);
        __nv_bfloat16 hb = __float2bfloat16(v.y);
        __nv_bfloat162 h; h.x = ha; h.y = hb;
        __nv_bfloat162 l;
        l.x = __float2bfloat16(v.x - __bfloat162float(ha));
        l.y = __float2bfloat16(v.y - __bfloat162float(hb));
        h2[i] = h;
        l2[i] = l;
    }
}

// ---------------------------------------------------------------------------
// GEMM: out = x @ W^T.
//   MAIN=false: router logits, 3-term bf16 split (selection-exact):
//               xh*wrh + xh*wrl + xl*wrh                     (BM=64, BN=128)
//   MAIN=true : main GEMM, single-term fp16 (w prescaled x1024):
//               xh*wh, then *1/1024 + b0 + rank-one epilogue (BM=128, BN=256)
// 8 warps = 2(m) x 4(n); cp.async 4-stage pipeline, two chunks resident;
// fragment double-buffering with cross-chunk ldsm lookahead.
// ---------------------------------------------------------------------------
template <int TBM, int TBN, int NSTG, int NSEG, bool MAIN>
__global__ void __launch_bounds__(256, 1)
gemm_kernel(const float* __restrict__ b0v, const float* __restrict__ u,
            float* __restrict__ out) {
    static_assert(NSTG >= 3, "need two chunks resident");
    constexpr int NTH = 256;
    constexpr int WMN = 2, WNN = 4;
    constexpr int WM  = TBM / WMN;
    constexpr int WN  = TBN / WNN;
    constexpr int MT  = WM / 16;
    constexpr int NT2 = WN / 16;
    constexpr int NT8 = WN / 8;
    constexpr int A_B = TBM * 128;
    constexpr int B_B = TBN * 128;
    constexpr int STG = A_B + B_B;
    constexpr int NCH  = NSEG * (IN / BK);    // 64 (main) / 192 (router)

    extern __shared__ __align__(1024) char smem[];
    const uint32_t smem_base = smem_u32(smem);

    const int tid    = threadIdx.x;
    const int wid    = tid >> 5;
    const int lane   = tid & 31;
    const int warp_m = wid & 1;
    const int warp_n = wid >> 1;

    // group-swizzled CTA rasterization (L2 reuse)
    constexpr int GM = 16;
    const int num_n = MAIN ? (OUT / TBN) : 1;
    const int per_group = GM * num_n;
    const int id = blockIdx.x;
    const int m_tile = (id / per_group) * GM + (id % per_group) % GM;
    const int n_tile = (id % per_group) / GM;
    const int m0 = m_tile * TBM;
    const int n0 = n_tile * TBN;

    const void* Aseg[NSEG];
    const void* Bseg[NSEG];
    if (MAIN) {
        Aseg[0] = g_xh;
        Bseg[0] = g_wh;
    } else {
        Aseg[0] = g_xhi;  Aseg[1 % NSEG] = g_xhi;  Aseg[NSEG - 1] = g_xlo;
        Bseg[0] = g_wrhi; Bseg[1 % NSEG] = g_wrlo; Bseg[NSEG - 1] = g_wrhi;
    }

    auto load_chunk = [&](int chunk, int stage) {
        const int seg = (NSEG == 1) ? 0 : (chunk >> 6);   // / (IN/BK)
        const int kc  = chunk & 63;
        const uint16_t* Ap = (const uint16_t*)Aseg[seg] + (size_t)m0 * IN + kc * BK;
        const uint16_t* Bp = (const uint16_t*)Bseg[seg] + (size_t)n0 * IN + kc * BK;
        const uint32_t sA = smem_base + stage * STG;
        const uint32_t sB = sA + A_B;
#pragma unroll
        for (int it = 0; it < (TBM * 8) / NTH; it++) {
            int s = tid + it * NTH;
            int row = s >> 3, c = s & 7;
            CP_ASYNC16(sA + SWZ128((uint32_t)(row * 128 + c * 16)),
                       (const void*)(Ap + (size_t)row * IN + c * 8));
        }
#pragma unroll
        for (int it = 0; it < (TBN * 8) / NTH; it++) {
            int s = tid + it * NTH;
            int row = s >> 3, c = s & 7;
            CP_ASYNC16(sB + SWZ128((uint32_t)(row * 128 + c * 16)),
                       (const void*)(Bp + (size_t)row * IN + c * 8));
        }
    };

    // ldmatrix per-thread addressing
    const int xorv = lane & 7;
    const int a_hi = lane >> 4;
    const int b_hi = (lane >> 3) & 1;
    uint32_t a_row[MT], b_row[NT2];
#pragma unroll
    for (int mt = 0; mt < MT; mt++)
        a_row[mt] = (uint32_t)((warp_m * WM + mt * 16 + (lane & 15)) * 128);
#pragma unroll
    for (int nt2 = 0; nt2 < NT2; nt2++)
        b_row[nt2] = (uint32_t)(A_B +
                     (warp_n * WN + nt2 * 16 + ((lane & 7) | ((lane & 16) >> 1))) * 128);

    auto ldfrags = [&](uint32_t sbase, int ks, uint32_t (*af)[4], uint32_t (*bf)[4]) {
        const uint32_t ach = (uint32_t)((ks * 2 + a_hi) ^ xorv) << 4;
        const uint32_t bch = (uint32_t)((ks * 2 + b_hi) ^ xorv) << 4;
#pragma unroll
        for (int mt = 0; mt < MT; mt++)
            ldsm_x4(af[mt], sbase + a_row[mt] + ach);
#pragma unroll
        for (int nt2 = 0; nt2 < NT2; nt2++)
            ldsm_x4(bf[nt2], sbase + b_row[nt2] + bch);
    };

    float acc[MT][NT8][4] = {};

    auto mma_all = [&](uint32_t (*af)[4], uint32_t (*bf)[4]) {
#pragma unroll
        for (int mt = 0; mt < MT; mt++)
#pragma unroll
            for (int nt2 = 0; nt2 < NT2; nt2++) {
                mma16816<MAIN>(acc[mt][nt2 * 2 + 0], af[mt], bf[nt2][0], bf[nt2][1]);
                mma16816<MAIN>(acc[mt][nt2 * 2 + 1], af[mt], bf[nt2][2], bf[nt2][3]);
            }
    };

    uint32_t afA[MT][4], bfA[NT2][4];   // ping
    uint32_t afB[MT][4], bfB[NT2][4];   // pong

    // prologue: load NSTG-1 chunks; make chunks 0 and 1 resident; preload ks0
#pragma unroll
    for (int s = 0; s < NSTG - 1; s++) { load_chunk(s, s); CP_COMMIT(); }
    cp_wait<NSTG - 3>();
    __syncthreads();
    ldfrags(smem_base, 0, afA, bfA);

    for (int i = 0; i < NCH; i++) {
        const int nxt = i + NSTG - 1;
        if (nxt < NCH) load_chunk(nxt, nxt % NSTG);
        CP_COMMIT();

        const uint32_t sb_i = smem_base + (i % NSTG) * STG;
        const uint32_t sb_n = smem_base + ((i + 1) % NSTG) * STG;

        // ks0: cur=A; prefetch ks1 -> B
        ldfrags(sb_i, 1, afB, bfB);
        mma_all(afA, bfA);
        // ks1: cur=B; prefetch ks2 -> A
        ldfrags(sb_i, 2, afA, bfA);
        mma_all(afB, bfB);
        // ks2: cur=A; prefetch ks3 -> B
        ldfrags(sb_i, 3, afB, bfB);
        mma_all(afA, bfA);
        // ks3: cur=B; prefetch next chunk's ks0 -> A (stale-safe on last iter)
        ldfrags(sb_n, 0, afA, bfA);
        mma_all(afB, bfB);

        // chunk i+2 resident; publish; safe to overwrite stage i next iter
        cp_wait<NSTG - 3>();
        __syncthreads();
    }

    // ---------------- epilogue (C frag: rows qrow,+8; cols qcol,+1) ---------
    const int qrow = lane >> 2;
    const int qcol = (lane & 3) * 2;

    if (MAIN) {
        // stage u[n0 .. n0+TBN) x POOLS into smem (padded stride 132 words)
        float* us = (float*)smem;
        constexpr int USTR = 132;
#pragma unroll 4
        for (int idx = tid; idx < TBN * (POOLS / 4); idx += NTH) {
            int o  = idx >> 5;           // 32 float4 per row
            int p4 = idx & 31;
            float4 v = *(const float4*)(u + (size_t)(n0 + o) * POOLS + p4 * 4);
            *(float4*)(us + o * USTR + p4 * 4) = v;
        }
        __syncthreads();

        float bo[NT8][2];
#pragma unroll
        for (int nt = 0; nt < NT8; nt++) {
            int o = n0 + warp_n * WN + nt * 8 + qcol;
            bo[nt][0] = b0v[o];
            bo[nt][1] = b0v[o + 1];
        }
#pragma unroll
        for (int mt = 0; mt < MT; mt++)
#pragma unroll
            for (int g = 0; g < 2; g++) {
                const int ntok = m0 + warp_m * WM + mt * 16 + g * 8 + qrow;
                const float d0 = g_dotv[2 * ntok], d1 = g_dotv[2 * ntok + 1];
                const int   p0 = g_idxv[2 * ntok], p1 = g_idxv[2 * ntok + 1];
#pragma unroll
                for (int nt = 0; nt < NT8; nt++) {
                    const int ol = warp_n * WN + nt * 8 + qcol;
                    float v0 = acc[mt][nt][g * 2 + 0] * INV_WSCALE + bo[nt][0]
                             + d0 * us[ol * USTR + p0]
                             + d1 * us[ol * USTR + p1];
                    float v1 = acc[mt][nt][g * 2 + 1] * INV_WSCALE + bo[nt][1]
                             + d0 * us[(ol + 1) * USTR + p0]
                             + d1 * us[(ol + 1) * USTR + p1];
                    *(float2*)(out + (size_t)ntok * OUT + n0 + ol) = make_float2(v0, v1);
                }
            }
    } else {
#pragma unroll
        for (int mt = 0; mt < MT; mt++)
#pragma unroll
            for (int g = 0; g < 2; g++) {
                const int ntok = m0 + warp_m * WM + mt * 16 + g * 8 + qrow;
#pragma unroll
                for (int nt = 0; nt < NT8; nt++) {
                    const int o = warp_n * WN + nt * 8 + qcol;
                    *(float2*)(g_logits + (size_t)ntok * POOLS + o) =
                        make_float2(acc[mt][nt][g * 2 + 0], acc[mt][nt][g * 2 + 1]);
                }
            }
    }
}

// ---------------------------------------------------------------------------
// Kernel 2: fp32 top-2 over logits + dot(x, svh[idx])  (exact fp32)
// (only the top-2 *set* matters: vals are unused; expert sum is symmetric)
// ---------------------------------------------------------------------------
__global__ void __launch_bounds__(128)
topk_kernel(const float* __restrict__ x, const float* __restrict__ svh) {
    const int n = blockIdx.x;
    const int tid = threadIdx.x;
    __shared__ float lg[POOLS];
    __shared__ int sp[2];
    __shared__ float red[2][128];

    lg[tid] = g_logits[(size_t)n * POOLS + tid];
    __syncthreads();

    if (tid == 0) {
        float bv0 = lg[0]; int bi0 = 0;
        float bv1 = -3.402823466e38f; int bi1 = 0;
        for (int t = 1; t < POOLS; t++) {
            float v = lg[t];
            if (v > bv0)      { bv1 = bv0; bi1 = bi0; bv0 = v; bi0 = t; }
            else if (v > bv1) { bv1 = v;  bi1 = t; }
        }
        sp[0] = bi0; sp[1] = bi1;
    }
    __syncthreads();

    const int p0 = sp[0], p1 = sp[1];
    const float4* xr = (const float4*)(x   + (size_t)n  * IN);
    const float4* s0 = (const float4*)(svh + (size_t)p0 * IN);
    const float4* s1 = (const float4*)(svh + (size_t)p1 * IN);
    float a0 = 0.f, a1 = 0.f;
    for (int i = tid; i < IN / 4; i += 128) {
        float4 xv = xr[i], v0 = s0[i], v1 = s1[i];
        a0 += xv.x * v0.x + xv.y * v0.y + xv.z * v0.z + xv.w * v0.w;
        a1 += xv.x * v1.x + xv.y * v1.y + xv.z * v1.z + xv.w * v1.w;
    }
    red[0][tid] = a0; red[1][tid] = a1;
    __syncthreads();
    for (int s = 64; s > 0; s >>= 1) {
        if (tid < s) { red[0][tid] += red[0][tid + s]; red[1][tid] += red[1][tid + s]; }
        __syncthreads();
    }
    if (tid == 0) {
        g_dotv[2 * n]     = red[0][0];
        g_dotv[2 * n + 1] = red[1][0];
        g_idxv[2 * n]     = p0;
        g_idxv[2 * n + 1] = p1;
    }
}

// ---------------------------------------------------------------------------
// Launch
// ---------------------------------------------------------------------------
extern "C" void kernel_launch(void* const* d_in, const int* in_sizes, int n_in,
                              void* d_out, int out_size) {
    const float* x   = (const float*)d_in[0];
    const float* w0  = (const float*)d_in[1];
    const float* b0  = (const float*)d_in[2];
    const float* wr  = (const float*)d_in[3];
    const float* u   = (const float*)d_in[4];
    const float* svh = (const float*)d_in[5];
    float* out = (float*)d_out;

    // main: BM=128, BN=256, 8 warps, 4 stages -> 192 KB smem
    constexpr int SMEM_MAIN = 4 * (128 + 256) * 128;        // 196,608 B
    // router: BM=64, BN=128, 8 warps, 4 stages -> 96 KB smem
    constexpr int SMEM_RTR  = 4 * (64 + 128) * 128;         //  98,304 B

    cudaFuncSetAttribute((const void*)gemm_kernel<128, 256, 4, 1, true>,
                         cudaFuncAttributeMaxDynamicSharedMemorySize, SMEM_MAIN);
    cudaFuncSetAttribute((const void*)gemm_kernel<64, 128, 4, 3, false>,
                         cudaFuncAttributeMaxDynamicSharedMemorySize, SMEM_RTR);

    // 0) precision splits
    split_x_kernel <<<1024, 256>>>(x,  NTOK * IN / 2);    // bf16 hi/lo + fp16
    split_w_kernel <<<512,  256>>>(w0, OUT * IN / 2);     // fp16(1024*w0), 1 term
    split_wr_kernel<<<64,   256>>>(wr, POOLS * IN / 2);   // bf16 hi/lo

    // 1) router logits = x @ wr^T  (3-term bf16: selection-exact; 128 CTAs)
    gemm_kernel<64, 128, 4, 3, false>
        <<<NTOK / 64, 256, SMEM_RTR>>>(nullptr, nullptr, nullptr);

    // 2) exact fp32 top-2 + dot(x, svh[idx])
    topk_kernel<<<NTOK, 128>>>(x, svh);

    // 3) main GEMM (single-term fp16, w prescaled) + bias + rank-one epilogue
    gemm_kernel<128, 256, 4, 1, true>
        <<<(NTOK / 128) * (OUT / 256), 256, SMEM_MAIN>>>(b0, u, out);
}